// round 1
// baseline (speedup 1.0000x reference)
#include <cuda_runtime.h>
#include <math.h>

#define NN 50000
#define FF 16
#define TT 12
#define HH 64
#define EE 1600000
#define CHX 192   // F*T channels of x per node
#define KK 80     // F + H

// ---------------- scratch (static device arrays; no allocation) ----------------
__device__ float g_deg[NN];
__device__ float g_dis[NN];
__device__ float g_self[NN];
__device__ int   g_cnt[NN];
__device__ int   g_row[NN];
__device__ int   g_cur[NN];
__device__ int   g_srcs[EE];
__device__ float g_ws[EE];
__device__ float g_Xp[NN * CHX];          // prop(x), layout [n][t][f]
__device__ float g_h[NN * HH];
__device__ float g_z[NN * HH];
__device__ float g_rh[NN * HH];
__device__ float g_Ah[NN * HH];
__device__ float g_Arh[NN * HH];
__device__ float g_hs[NN * TT * HH];      // [n][t][c]

// ---------------- helpers ----------------
__device__ __forceinline__ float fast_tanh(float x) {
    float y;
    asm("tanh.approx.f32 %0, %1;" : "=f"(y) : "f"(x));
    return y;
}
__device__ __forceinline__ float fast_sigmoid(float x) {
    return 0.5f * fast_tanh(0.5f * x) + 0.5f;
}

// ---------------- prologue kernels ----------------
__global__ void init_kernel() {
    int i = blockIdx.x * blockDim.x + threadIdx.x;
    if (i < NN * HH) g_h[i] = 0.0f;
    if (i < NN) { g_deg[i] = 0.0f; g_cnt[i] = 0; }
}

__global__ void deg_kernel(const int* __restrict__ ei, const float* __restrict__ ew) {
    int e = blockIdx.x * blockDim.x + threadIdx.x;
    if (e >= EE) return;
    int d = ei[EE + e];
    atomicAdd(&g_deg[d], ew[e]);
    atomicAdd(&g_cnt[d], 1);
}

__global__ void dis_kernel() {
    int i = blockIdx.x * blockDim.x + threadIdx.x;
    if (i >= NN) return;
    float r = rsqrtf(g_deg[i] + 1.0f);
    g_dis[i] = r;
    g_self[i] = r * r;
}

__global__ void scan_kernel() {
    __shared__ int wsum[32];
    __shared__ int carry;
    int tid = threadIdx.x, lane = tid & 31, wid = tid >> 5;
    if (tid == 0) carry = 0;
    __syncthreads();
    for (int base = 0; base < NN; base += 1024) {
        int i = base + tid;
        int v = (i < NN) ? g_cnt[i] : 0;
        int x = v;
        #pragma unroll
        for (int o = 1; o < 32; o <<= 1) {
            int y = __shfl_up_sync(0xffffffffu, x, o);
            if (lane >= o) x += y;
        }
        if (lane == 31) wsum[wid] = x;
        __syncthreads();
        if (tid < 32) {
            int s = wsum[tid];
            #pragma unroll
            for (int o = 1; o < 32; o <<= 1) {
                int y = __shfl_up_sync(0xffffffffu, s, o);
                if (tid >= o) s += y;
            }
            wsum[tid] = s;
        }
        __syncthreads();
        int tot = wsum[31];
        int excl = carry + x - v + (wid ? wsum[wid - 1] : 0);
        if (i < NN) { g_row[i] = excl; g_cur[i] = excl; }
        __syncthreads();
        if (tid == 0) carry += tot;
        __syncthreads();
    }
}

__global__ void fill_kernel(const int* __restrict__ ei, const float* __restrict__ ew) {
    int e = blockIdx.x * blockDim.x + threadIdx.x;
    if (e >= EE) return;
    int s = ei[e];
    int d = ei[EE + e];
    int p = atomicAdd(&g_cur[d], 1);
    g_srcs[p] = s;
    g_ws[p] = g_dis[s] * ew[e] * g_dis[d];
}

// propagate all 192 channels of x once. warp per node.
__global__ __launch_bounds__(256) void prop_x_kernel(const float* __restrict__ x) {
    int gw = (blockIdx.x * blockDim.x + threadIdx.x) >> 5;
    if (gw >= NN) return;
    int lane = threadIdx.x & 31;
    int st = g_row[gw], cnt = g_cnt[gw];
    float acc[6] = {0, 0, 0, 0, 0, 0};
    const int* sp = &g_srcs[st];
    const float* wp = &g_ws[st];
    for (int e = 0; e < cnt; e++) {
        int s = __ldg(&sp[e]);
        float w = __ldg(&wp[e]);
        const float* xr = &x[s * CHX];
        #pragma unroll
        for (int j = 0; j < 6; j++) acc[j] += w * __ldg(&xr[lane + 32 * j]);
    }
    float sn = g_self[gw];
    const float* xn = &x[gw * CHX];
    #pragma unroll
    for (int j = 0; j < 6; j++) {
        int c = lane + 32 * j;           // c = f*12 + t  (x layout [n][f][t])
        float v = acc[j] + sn * __ldg(&xn[c]);
        int f = c / 12;
        int t = c - f * 12;
        g_Xp[gw * CHX + t * FF + f] = v; // Xp layout [n][t][f]
    }
}

// propagate 64 channels: which==0: h -> Ah ; which==1: rh -> Arh. warp per node.
__global__ __launch_bounds__(256) void prop64_kernel(int which) {
    int gw = (blockIdx.x * blockDim.x + threadIdx.x) >> 5;
    if (gw >= NN) return;
    int lane = threadIdx.x & 31;
    const float* in = which ? g_rh : g_h;
    float* out = which ? g_Arh : g_Ah;
    int st = g_row[gw], cnt = g_cnt[gw];
    const int* sp = &g_srcs[st];
    const float* wp = &g_ws[st];
    float ax = 0.0f, ay = 0.0f;
    for (int e = 0; e < cnt; e++) {
        int s = __ldg(&sp[e]);
        float w = __ldg(&wp[e]);
        float2 v = *(const float2*)&in[s * HH + lane * 2];
        ax += w * v.x;
        ay += w * v.y;
    }
    float sn = g_self[gw];
    float2 v = *(const float2*)&in[gw * HH + lane * 2];
    ax += sn * v.x;
    ay += sn * v.y;
    *(float2*)&out[gw * HH + lane * 2] = make_float2(ax, ay);
}

// ---------------- gate kernels ----------------
// z/r gates: for 64 nodes, compute z = sigmoid([Xp_t | Ah] @ Wz + bz),
// r = sigmoid([Xp_t | Ah] @ Wr + br), store z and rh = r*h.
__global__ __launch_bounds__(256) void zr_kernel(const float* __restrict__ Wz, const float* __restrict__ bz,
                                                 const float* __restrict__ Wr, const float* __restrict__ br,
                                                 int t) {
    __shared__ __align__(16) float As[KK][68];
    int tid = threadIdx.x;
    int n0 = blockIdx.x * 64;
    // stage x part (rows 0..15)
    {
        int m = tid >> 2, fq = tid & 3;
        int n = n0 + m;
        float4 v = (n < NN) ? *(const float4*)&g_Xp[n * CHX + t * FF + fq * 4]
                            : make_float4(0, 0, 0, 0);
        As[fq * 4 + 0][m] = v.x; As[fq * 4 + 1][m] = v.y;
        As[fq * 4 + 2][m] = v.z; As[fq * 4 + 3][m] = v.w;
    }
    // stage Ah part (rows 16..79)
    #pragma unroll
    for (int rep = 0; rep < 4; rep++) {
        int idx = rep * 256 + tid;
        int m = idx >> 4, jq = idx & 15;
        int n = n0 + m;
        float4 v = (n < NN) ? *(const float4*)&g_Ah[n * HH + jq * 4]
                            : make_float4(0, 0, 0, 0);
        As[16 + jq * 4 + 0][m] = v.x; As[16 + jq * 4 + 1][m] = v.y;
        As[16 + jq * 4 + 2][m] = v.z; As[16 + jq * 4 + 3][m] = v.w;
    }
    __syncthreads();

    int ct = tid & 15, mt = tid >> 4;
    int c0 = ct * 8, m0 = mt * 4;
    bool isz = (c0 < HH);
    const float* W = isz ? Wz : Wr;
    int cc = c0 & 63;

    float acc[4][8];
    #pragma unroll
    for (int mi = 0; mi < 4; mi++)
        #pragma unroll
        for (int ci = 0; ci < 8; ci++) acc[mi][ci] = 0.0f;

    #pragma unroll 4
    for (int k = 0; k < KK; k++) {
        float4 a = *(const float4*)&As[k][m0];
        float4 b0 = __ldg((const float4*)&W[k * HH + cc]);
        float4 b1 = __ldg((const float4*)&W[k * HH + cc + 4]);
        float av[4] = {a.x, a.y, a.z, a.w};
        float bv[8] = {b0.x, b0.y, b0.z, b0.w, b1.x, b1.y, b1.z, b1.w};
        #pragma unroll
        for (int mi = 0; mi < 4; mi++)
            #pragma unroll
            for (int ci = 0; ci < 8; ci++)
                acc[mi][ci] += av[mi] * bv[ci];
    }

    #pragma unroll
    for (int mi = 0; mi < 4; mi++) {
        int n = n0 + m0 + mi;
        if (n < NN) {
            #pragma unroll
            for (int ci = 0; ci < 8; ci++) {
                int c = cc + ci;
                float bias = isz ? __ldg(&bz[c]) : __ldg(&br[c]);
                float s = fast_sigmoid(acc[mi][ci] + bias);
                if (isz) g_z[n * HH + c] = s;
                else     g_rh[n * HH + c] = s * g_h[n * HH + c];
            }
        }
    }
}

// hc = tanh([Xp_t | Arh] @ Wh + bh); h = z*h + (1-z)*hc; hs[n][t] = h
__global__ __launch_bounds__(256) void upd_kernel(const float* __restrict__ Wh, const float* __restrict__ bh,
                                                  int t) {
    __shared__ __align__(16) float As[KK][68];
    int tid = threadIdx.x;
    int n0 = blockIdx.x * 64;
    {
        int m = tid >> 2, fq = tid & 3;
        int n = n0 + m;
        float4 v = (n < NN) ? *(const float4*)&g_Xp[n * CHX + t * FF + fq * 4]
                            : make_float4(0, 0, 0, 0);
        As[fq * 4 + 0][m] = v.x; As[fq * 4 + 1][m] = v.y;
        As[fq * 4 + 2][m] = v.z; As[fq * 4 + 3][m] = v.w;
    }
    #pragma unroll
    for (int rep = 0; rep < 4; rep++) {
        int idx = rep * 256 + tid;
        int m = idx >> 4, jq = idx & 15;
        int n = n0 + m;
        float4 v = (n < NN) ? *(const float4*)&g_Arh[n * HH + jq * 4]
                            : make_float4(0, 0, 0, 0);
        As[16 + jq * 4 + 0][m] = v.x; As[16 + jq * 4 + 1][m] = v.y;
        As[16 + jq * 4 + 2][m] = v.z; As[16 + jq * 4 + 3][m] = v.w;
    }
    __syncthreads();

    int ct = tid & 15, mt = tid >> 4;
    int c0 = ct * 4, m0 = mt * 4;

    float acc[4][4];
    #pragma unroll
    for (int mi = 0; mi < 4; mi++)
        #pragma unroll
        for (int ci = 0; ci < 4; ci++) acc[mi][ci] = 0.0f;

    #pragma unroll 4
    for (int k = 0; k < KK; k++) {
        float4 a = *(const float4*)&As[k][m0];
        float4 b = __ldg((const float4*)&Wh[k * HH + c0]);
        float av[4] = {a.x, a.y, a.z, a.w};
        float bv[4] = {b.x, b.y, b.z, b.w};
        #pragma unroll
        for (int mi = 0; mi < 4; mi++)
            #pragma unroll
            for (int ci = 0; ci < 4; ci++)
                acc[mi][ci] += av[mi] * bv[ci];
    }

    #pragma unroll
    for (int mi = 0; mi < 4; mi++) {
        int n = n0 + m0 + mi;
        if (n < NN) {
            #pragma unroll
            for (int ci = 0; ci < 4; ci++) {
                int c = c0 + ci;
                float hc = fast_tanh(acc[mi][ci] + __ldg(&bh[c]));
                float z = g_z[n * HH + c];
                float h = g_h[n * HH + c];
                float hn = z * h + (1.0f - z) * hc;
                g_h[n * HH + c] = hn;
                g_hs[n * (TT * HH) + t * HH + c] = hn;
            }
        }
    }
}

// ---------------- attention + FC ----------------
__global__ __launch_bounds__(256) void attn_kernel(const float* __restrict__ Wa, const float* __restrict__ ba,
                                                   const float* __restrict__ cv, const float* __restrict__ Wfc,
                                                   const float* __restrict__ bfc, float* __restrict__ out) {
    __shared__ float Wa_s[4096];
    __shared__ float ba_s[64], cv_s[64], fc_s[64];
    __shared__ float al_s[8][TT];
    int tid = threadIdx.x;
    for (int i = tid; i < 4096; i += 256) Wa_s[i] = Wa[i];
    if (tid < 64) { ba_s[tid] = ba[tid]; cv_s[tid] = cv[tid]; fc_s[tid] = Wfc[tid]; }
    __syncthreads();

    int warp = tid >> 5, lane = tid & 31;
    int n = blockIdx.x * 8 + warp;
    if (n >= NN) return;
    const float* hb = &g_hs[n * (TT * HH)];

    for (int t = 0; t < TT; t++) {
        float hv0 = __ldg(&hb[t * HH + lane]);
        float hv1 = __ldg(&hb[t * HH + lane + 32]);
        float a0 = ba_s[lane], a1 = ba_s[lane + 32];
        #pragma unroll
        for (int j = 0; j < 32; j++) {
            float hj = __shfl_sync(0xffffffffu, hv0, j);
            a0 += hj * Wa_s[j * HH + lane];
            a1 += hj * Wa_s[j * HH + lane + 32];
        }
        #pragma unroll
        for (int j = 0; j < 32; j++) {
            float hj = __shfl_sync(0xffffffffu, hv1, j);
            a0 += hj * Wa_s[(j + 32) * HH + lane];
            a1 += hj * Wa_s[(j + 32) * HH + lane + 32];
        }
        float al = fast_tanh(a0) * cv_s[lane] + fast_tanh(a1) * cv_s[lane + 32];
        #pragma unroll
        for (int o = 16; o; o >>= 1) al += __shfl_xor_sync(0xffffffffu, al, o);
        if (lane == 0) al_s[warp][t] = al;
    }
    __syncwarp();

    float mx = -1e30f;
    for (int t = 0; t < TT; t++) mx = fmaxf(mx, al_s[warp][t]);
    float ssum = 0.0f;
    for (int t = 0; t < TT; t++) ssum += __expf(al_s[warp][t] - mx);
    float inv = 1.0f / ssum;

    float c0 = 0.0f, c1 = 0.0f;
    for (int t = 0; t < TT; t++) {
        float w = __expf(al_s[warp][t] - mx) * inv;
        c0 += w * __ldg(&hb[t * HH + lane]);
        c1 += w * __ldg(&hb[t * HH + lane + 32]);
    }
    float o = c0 * fc_s[lane] + c1 * fc_s[lane + 32];
    #pragma unroll
    for (int off = 16; off; off >>= 1) o += __shfl_xor_sync(0xffffffffu, o, off);
    if (lane == 0) out[n] = o + bfc[0];
}

// ---------------- launcher ----------------
extern "C" void kernel_launch(void* const* d_in, const int* in_sizes, int n_in,
                              void* d_out, int out_size) {
    const float* x   = (const float*)d_in[0];
    const int*   ei  = (const int*)d_in[1];
    const float* ew  = (const float*)d_in[2];
    const float* Wz  = (const float*)d_in[3];
    const float* bz  = (const float*)d_in[4];
    const float* Wr  = (const float*)d_in[5];
    const float* br  = (const float*)d_in[6];
    const float* Wh  = (const float*)d_in[7];
    const float* bh  = (const float*)d_in[8];
    const float* Wa  = (const float*)d_in[9];
    const float* ba  = (const float*)d_in[10];
    const float* cv  = (const float*)d_in[11];
    const float* Wfc = (const float*)d_in[12];
    const float* bfc = (const float*)d_in[13];
    float* out = (float*)d_out;

    int eb = (EE + 255) / 256;            // 6250
    int nb = (NN + 255) / 256;            // 196
    int wb = (NN * 32 + 255) / 256;       // 6250 (warp per node)
    int gb = (NN + 63) / 64;              // 782  (GEMM tiles)
    int ab = (NN + 7) / 8;                // 6250 (attention, 8 nodes/block)

    init_kernel<<<(NN * HH + 255) / 256, 256>>>();
    deg_kernel<<<eb, 256>>>(ei, ew);
    dis_kernel<<<nb, 256>>>();
    scan_kernel<<<1, 1024>>>();
    fill_kernel<<<eb, 256>>>(ei, ew);
    prop_x_kernel<<<wb, 256>>>(x);

    for (int t = 0; t < TT; t++) {
        prop64_kernel<<<wb, 256>>>(0);                 // Ah = prop(h)
        zr_kernel<<<gb, 256>>>(Wz, bz, Wr, br, t);     // z, rh = sigmoid(.)*h
        prop64_kernel<<<wb, 256>>>(1);                 // Arh = prop(rh)
        upd_kernel<<<gb, 256>>>(Wh, bh, t);            // h update + hs store
    }

    attn_kernel<<<ab, 256>>>(Wa, ba, cv, Wfc, bfc, out);
}

// round 2
// speedup vs baseline: 1.0273x; 1.0273x over previous
#include <cuda_runtime.h>
#include <cuda_fp16.h>
#include <math.h>

#define NN 50000
#define FF 16
#define TT 12
#define HH 64
#define EE 1600000
#define CHX 192   // F*T channels of x per node
#define KK 80     // F + H
#define SCAN_B 49 // ceil(NN/1024)

// ---------------- scratch (static device arrays; no allocation) ----------------
__device__ float g_deg[NN];
__device__ float g_dis[NN];
__device__ float g_self[NN];
__device__ int   g_cnt[NN];
__device__ int   g_row[NN];
__device__ int   g_cur[NN];
__device__ int   g_part[64];
__device__ int   g_srcs[EE];
__device__ float g_ws[EE];
__device__ __half g_x16[NN * CHX];
__device__ float g_Xp[NN * CHX];          // prop(x), layout [n][t][f]
__device__ float g_h[NN * HH];
__device__ __half g_h16[NN * HH];
__device__ float g_z[NN * HH];
__device__ __half g_rh16[NN * HH];
__device__ float g_Ah[NN * HH];
__device__ float g_Arh[NN * HH];
__device__ float g_hs[NN * TT * HH];      // [n][t][c]

// ---------------- helpers ----------------
__device__ __forceinline__ float fast_tanh(float x) {
    float y;
    asm("tanh.approx.f32 %0, %1;" : "=f"(y) : "f"(x));
    return y;
}
__device__ __forceinline__ float fast_sigmoid(float x) {
    return 0.5f * fast_tanh(0.5f * x) + 0.5f;
}

// ---------------- prologue kernels ----------------
__global__ void init_kernel() {
    int i = blockIdx.x * blockDim.x + threadIdx.x;
    if (i < NN * HH) { g_h[i] = 0.0f; g_h16[i] = __float2half(0.0f); }
    if (i < NN) { g_deg[i] = 0.0f; g_cnt[i] = 0; }
}

__global__ void convx_kernel(const float* __restrict__ x) {
    int i = blockIdx.x * blockDim.x + threadIdx.x;
    int i4 = i * 4;
    if (i4 + 3 < NN * CHX) {
        float4 v = __ldg((const float4*)&x[i4]);
        __half2* o = (__half2*)&g_x16[i4];
        o[0] = __floats2half2_rn(v.x, v.y);
        o[1] = __floats2half2_rn(v.z, v.w);
    }
}

__global__ void deg_kernel(const int* __restrict__ ei, const float* __restrict__ ew) {
    int e = blockIdx.x * blockDim.x + threadIdx.x;
    if (e >= EE) return;
    int d = ei[EE + e];
    atomicAdd(&g_deg[d], ew[e]);
    atomicAdd(&g_cnt[d], 1);
}

__global__ void dis_kernel() {
    int i = blockIdx.x * blockDim.x + threadIdx.x;
    if (i >= NN) return;
    float r = rsqrtf(g_deg[i] + 1.0f);
    g_dis[i] = r;
    g_self[i] = r * r;
}

// hierarchical scan: block partial sums -> tiny scan -> per-block offsets
__global__ void part_kernel() {
    __shared__ int ws[32];
    int tid = threadIdx.x, lane = tid & 31, wid = tid >> 5;
    int i = blockIdx.x * 1024 + tid;
    int v = (i < NN) ? g_cnt[i] : 0;
    #pragma unroll
    for (int o = 16; o; o >>= 1) v += __shfl_xor_sync(0xffffffffu, v, o);
    if (lane == 0) ws[wid] = v;
    __syncthreads();
    if (tid < 32) {
        int s = ws[tid];
        #pragma unroll
        for (int o = 16; o; o >>= 1) s += __shfl_xor_sync(0xffffffffu, s, o);
        if (tid == 0) g_part[blockIdx.x] = s;
    }
}

__global__ void scanpart_kernel() {
    if (threadIdx.x == 0) {
        int run = 0;
        for (int b = 0; b < SCAN_B; b++) { int v = g_part[b]; g_part[b] = run; run += v; }
    }
}

__global__ void offs_kernel() {
    __shared__ int wsum[32];
    int tid = threadIdx.x, lane = tid & 31, wid = tid >> 5;
    int i = blockIdx.x * 1024 + tid;
    int v = (i < NN) ? g_cnt[i] : 0;
    int x = v;
    #pragma unroll
    for (int o = 1; o < 32; o <<= 1) {
        int y = __shfl_up_sync(0xffffffffu, x, o);
        if (lane >= o) x += y;
    }
    if (lane == 31) wsum[wid] = x;
    __syncthreads();
    if (tid < 32) {
        int s = wsum[tid];
        #pragma unroll
        for (int o = 1; o < 32; o <<= 1) {
            int y = __shfl_up_sync(0xffffffffu, s, o);
            if (tid >= o) s += y;
        }
        wsum[tid] = s;
    }
    __syncthreads();
    int excl = g_part[blockIdx.x] + x - v + (wid ? wsum[wid - 1] : 0);
    if (i < NN) { g_row[i] = excl; g_cur[i] = excl; }
}

__global__ void fill_kernel(const int* __restrict__ ei, const float* __restrict__ ew) {
    int e = blockIdx.x * blockDim.x + threadIdx.x;
    if (e >= EE) return;
    int s = ei[e];
    int d = ei[EE + e];
    int p = atomicAdd(&g_cur[d], 1);
    g_srcs[p] = s;
    g_ws[p] = g_dis[s] * ew[e] * g_dis[d];
}

// propagate all 192 channels of x once (fp16 gather). warp per node.
__global__ __launch_bounds__(256) void prop_x_kernel() {
    int gw = (blockIdx.x * blockDim.x + threadIdx.x) >> 5;
    if (gw >= NN) return;
    int lane = threadIdx.x & 31;
    int st = g_row[gw], cnt = g_cnt[gw];
    float acc[6] = {0, 0, 0, 0, 0, 0};
    const int* sp = &g_srcs[st];
    const float* wp = &g_ws[st];
    int e = 0;
    for (; e + 2 <= cnt; e += 2) {
        int s0 = __ldg(&sp[e]), s1 = __ldg(&sp[e + 1]);
        float w0 = __ldg(&wp[e]), w1 = __ldg(&wp[e + 1]);
        const __half2* r0 = (const __half2*)&g_x16[s0 * CHX];
        const __half2* r1 = (const __half2*)&g_x16[s1 * CHX];
        #pragma unroll
        for (int j = 0; j < 3; j++) {
            float2 f0 = __half22float2(r0[lane + 32 * j]);
            float2 f1 = __half22float2(r1[lane + 32 * j]);
            acc[2 * j]     += w0 * f0.x + w1 * f1.x;
            acc[2 * j + 1] += w0 * f0.y + w1 * f1.y;
        }
    }
    for (; e < cnt; e++) {
        int s = __ldg(&sp[e]);
        float w = __ldg(&wp[e]);
        const __half2* r0 = (const __half2*)&g_x16[s * CHX];
        #pragma unroll
        for (int j = 0; j < 3; j++) {
            float2 f0 = __half22float2(r0[lane + 32 * j]);
            acc[2 * j]     += w * f0.x;
            acc[2 * j + 1] += w * f0.y;
        }
    }
    float sn = g_self[gw];
    const __half2* xn = (const __half2*)&g_x16[gw * CHX];
    #pragma unroll
    for (int j = 0; j < 3; j++) {
        float2 f0 = __half22float2(xn[lane + 32 * j]);
        #pragma unroll
        for (int k = 0; k < 2; k++) {
            int c = 2 * (lane + 32 * j) + k;      // c = f*12 + t (x layout [n][f][t])
            float v = acc[2 * j + k] + sn * (k ? f0.y : f0.x);
            int f = c / 12;
            int t = c - f * 12;
            g_Xp[gw * CHX + t * FF + f] = v;       // Xp layout [n][t][f]
        }
    }
}

// propagate 64 channels (fp16 gather): which==0: h16 -> Ah ; which==1: rh16 -> Arh.
__global__ __launch_bounds__(256) void prop64_kernel(int which) {
    int gw = (blockIdx.x * blockDim.x + threadIdx.x) >> 5;
    if (gw >= NN) return;
    int lane = threadIdx.x & 31;
    const __half2* in = (const __half2*)(which ? g_rh16 : g_h16);
    float* out = which ? g_Arh : g_Ah;
    int st = g_row[gw], cnt = g_cnt[gw];
    const int* sp = &g_srcs[st];
    const float* wp = &g_ws[st];
    float ax = 0.0f, ay = 0.0f;
    int e = 0;
    for (; e + 4 <= cnt; e += 4) {
        int s0 = __ldg(&sp[e]), s1 = __ldg(&sp[e + 1]);
        int s2 = __ldg(&sp[e + 2]), s3 = __ldg(&sp[e + 3]);
        float w0 = __ldg(&wp[e]), w1 = __ldg(&wp[e + 1]);
        float w2 = __ldg(&wp[e + 2]), w3 = __ldg(&wp[e + 3]);
        float2 v0 = __half22float2(in[s0 * 32 + lane]);
        float2 v1 = __half22float2(in[s1 * 32 + lane]);
        float2 v2 = __half22float2(in[s2 * 32 + lane]);
        float2 v3 = __half22float2(in[s3 * 32 + lane]);
        ax += w0 * v0.x + w1 * v1.x + w2 * v2.x + w3 * v3.x;
        ay += w0 * v0.y + w1 * v1.y + w2 * v2.y + w3 * v3.y;
    }
    for (; e < cnt; e++) {
        int s = __ldg(&sp[e]);
        float w = __ldg(&wp[e]);
        float2 v = __half22float2(in[s * 32 + lane]);
        ax += w * v.x;
        ay += w * v.y;
    }
    float sn = g_self[gw];
    float2 v = __half22float2(in[gw * 32 + lane]);
    ax += sn * v.x;
    ay += sn * v.y;
    *(float2*)&out[gw * HH + lane * 2] = make_float2(ax, ay);
}

// ---------------- gate kernels ----------------
__global__ __launch_bounds__(256) void zr_kernel(const float* __restrict__ Wz, const float* __restrict__ bz,
                                                 const float* __restrict__ Wr, const float* __restrict__ br,
                                                 int t) {
    __shared__ __align__(16) float As[KK][68];
    int tid = threadIdx.x;
    int n0 = blockIdx.x * 64;
    {
        int m = tid >> 2, fq = tid & 3;
        int n = n0 + m;
        float4 v = (n < NN) ? *(const float4*)&g_Xp[n * CHX + t * FF + fq * 4]
                            : make_float4(0, 0, 0, 0);
        As[fq * 4 + 0][m] = v.x; As[fq * 4 + 1][m] = v.y;
        As[fq * 4 + 2][m] = v.z; As[fq * 4 + 3][m] = v.w;
    }
    #pragma unroll
    for (int rep = 0; rep < 4; rep++) {
        int idx = rep * 256 + tid;
        int m = idx >> 4, jq = idx & 15;
        int n = n0 + m;
        float4 v = (n < NN) ? *(const float4*)&g_Ah[n * HH + jq * 4]
                            : make_float4(0, 0, 0, 0);
        As[16 + jq * 4 + 0][m] = v.x; As[16 + jq * 4 + 1][m] = v.y;
        As[16 + jq * 4 + 2][m] = v.z; As[16 + jq * 4 + 3][m] = v.w;
    }
    __syncthreads();

    int ct = tid & 15, mt = tid >> 4;
    int c0 = ct * 8, m0 = mt * 4;
    bool isz = (c0 < HH);
    const float* W = isz ? Wz : Wr;
    int cc = c0 & 63;

    float acc[4][8];
    #pragma unroll
    for (int mi = 0; mi < 4; mi++)
        #pragma unroll
        for (int ci = 0; ci < 8; ci++) acc[mi][ci] = 0.0f;

    #pragma unroll 4
    for (int k = 0; k < KK; k++) {
        float4 a = *(const float4*)&As[k][m0];
        float4 b0 = __ldg((const float4*)&W[k * HH + cc]);
        float4 b1 = __ldg((const float4*)&W[k * HH + cc + 4]);
        float av[4] = {a.x, a.y, a.z, a.w};
        float bv[8] = {b0.x, b0.y, b0.z, b0.w, b1.x, b1.y, b1.z, b1.w};
        #pragma unroll
        for (int mi = 0; mi < 4; mi++)
            #pragma unroll
            for (int ci = 0; ci < 8; ci++)
                acc[mi][ci] += av[mi] * bv[ci];
    }

    #pragma unroll
    for (int mi = 0; mi < 4; mi++) {
        int n = n0 + m0 + mi;
        if (n < NN) {
            #pragma unroll
            for (int ci = 0; ci < 8; ci++) {
                int c = cc + ci;
                float bias = isz ? __ldg(&bz[c]) : __ldg(&br[c]);
                float s = fast_sigmoid(acc[mi][ci] + bias);
                if (isz) g_z[n * HH + c] = s;
                else     g_rh16[n * HH + c] = __float2half_rn(s * g_h[n * HH + c]);
            }
        }
    }
}

__global__ __launch_bounds__(256) void upd_kernel(const float* __restrict__ Wh, const float* __restrict__ bh,
                                                  int t) {
    __shared__ __align__(16) float As[KK][68];
    int tid = threadIdx.x;
    int n0 = blockIdx.x * 64;
    {
        int m = tid >> 2, fq = tid & 3;
        int n = n0 + m;
        float4 v = (n < NN) ? *(const float4*)&g_Xp[n * CHX + t * FF + fq * 4]
                            : make_float4(0, 0, 0, 0);
        As[fq * 4 + 0][m] = v.x; As[fq * 4 + 1][m] = v.y;
        As[fq * 4 + 2][m] = v.z; As[fq * 4 + 3][m] = v.w;
    }
    #pragma unroll
    for (int rep = 0; rep < 4; rep++) {
        int idx = rep * 256 + tid;
        int m = idx >> 4, jq = idx & 15;
        int n = n0 + m;
        float4 v = (n < NN) ? *(const float4*)&g_Arh[n * HH + jq * 4]
                            : make_float4(0, 0, 0, 0);
        As[16 + jq * 4 + 0][m] = v.x; As[16 + jq * 4 + 1][m] = v.y;
        As[16 + jq * 4 + 2][m] = v.z; As[16 + jq * 4 + 3][m] = v.w;
    }
    __syncthreads();

    int ct = tid & 15, mt = tid >> 4;
    int c0 = ct * 4, m0 = mt * 4;

    float acc[4][4];
    #pragma unroll
    for (int mi = 0; mi < 4; mi++)
        #pragma unroll
        for (int ci = 0; ci < 4; ci++) acc[mi][ci] = 0.0f;

    #pragma unroll 4
    for (int k = 0; k < KK; k++) {
        float4 a = *(const float4*)&As[k][m0];
        float4 b = __ldg((const float4*)&Wh[k * HH + c0]);
        float av[4] = {a.x, a.y, a.z, a.w};
        float bv[4] = {b.x, b.y, b.z, b.w};
        #pragma unroll
        for (int mi = 0; mi < 4; mi++)
            #pragma unroll
            for (int ci = 0; ci < 4; ci++)
                acc[mi][ci] += av[mi] * bv[ci];
    }

    #pragma unroll
    for (int mi = 0; mi < 4; mi++) {
        int n = n0 + m0 + mi;
        if (n < NN) {
            #pragma unroll
            for (int ci = 0; ci < 4; ci++) {
                int c = c0 + ci;
                float hc = fast_tanh(acc[mi][ci] + __ldg(&bh[c]));
                float z = g_z[n * HH + c];
                float h = g_h[n * HH + c];
                float hn = z * h + (1.0f - z) * hc;
                g_h[n * HH + c] = hn;
                g_h16[n * HH + c] = __float2half_rn(hn);
                g_hs[n * (TT * HH) + t * HH + c] = hn;
            }
        }
    }
}

// ---------------- attention + FC ----------------
__global__ __launch_bounds__(256) void attn_kernel(const float* __restrict__ Wa, const float* __restrict__ ba,
                                                   const float* __restrict__ cv, const float* __restrict__ Wfc,
                                                   const float* __restrict__ bfc, float* __restrict__ out) {
    __shared__ float Wa_s[4096];
    __shared__ float ba_s[64], cv_s[64], fc_s[64];
    __shared__ float al_s[8][TT];
    int tid = threadIdx.x;
    for (int i = tid; i < 4096; i += 256) Wa_s[i] = Wa[i];
    if (tid < 64) { ba_s[tid] = ba[tid]; cv_s[tid] = cv[tid]; fc_s[tid] = Wfc[tid]; }
    __syncthreads();

    int warp = tid >> 5, lane = tid & 31;
    int n = blockIdx.x * 8 + warp;
    if (n >= NN) return;
    const float* hb = &g_hs[n * (TT * HH)];

    for (int t = 0; t < TT; t++) {
        float hv0 = __ldg(&hb[t * HH + lane]);
        float hv1 = __ldg(&hb[t * HH + lane + 32]);
        float a0 = ba_s[lane], a1 = ba_s[lane + 32];
        #pragma unroll
        for (int j = 0; j < 32; j++) {
            float hj = __shfl_sync(0xffffffffu, hv0, j);
            a0 += hj * Wa_s[j * HH + lane];
            a1 += hj * Wa_s[j * HH + lane + 32];
        }
        #pragma unroll
        for (int j = 0; j < 32; j++) {
            float hj = __shfl_sync(0xffffffffu, hv1, j);
            a0 += hj * Wa_s[(j + 32) * HH + lane];
            a1 += hj * Wa_s[(j + 32) * HH + lane + 32];
        }
        float al = fast_tanh(a0) * cv_s[lane] + fast_tanh(a1) * cv_s[lane + 32];
        #pragma unroll
        for (int o = 16; o; o >>= 1) al += __shfl_xor_sync(0xffffffffu, al, o);
        if (lane == 0) al_s[warp][t] = al;
    }
    __syncwarp();

    float mx = -1e30f;
    for (int t = 0; t < TT; t++) mx = fmaxf(mx, al_s[warp][t]);
    float ssum = 0.0f;
    for (int t = 0; t < TT; t++) ssum += __expf(al_s[warp][t] - mx);
    float inv = 1.0f / ssum;

    float c0 = 0.0f, c1 = 0.0f;
    for (int t = 0; t < TT; t++) {
        float w = __expf(al_s[warp][t] - mx) * inv;
        c0 += w * __ldg(&hb[t * HH + lane]);
        c1 += w * __ldg(&hb[t * HH + lane + 32]);
    }
    float o = c0 * fc_s[lane] + c1 * fc_s[lane + 32];
    #pragma unroll
    for (int off = 16; off; off >>= 1) o += __shfl_xor_sync(0xffffffffu, o, off);
    if (lane == 0) out[n] = o + bfc[0];
}

// ---------------- launcher ----------------
extern "C" void kernel_launch(void* const* d_in, const int* in_sizes, int n_in,
                              void* d_out, int out_size) {
    const float* x   = (const float*)d_in[0];
    const int*   ei  = (const int*)d_in[1];
    const float* ew  = (const float*)d_in[2];
    const float* Wz  = (const float*)d_in[3];
    const float* bz  = (const float*)d_in[4];
    const float* Wr  = (const float*)d_in[5];
    const float* br  = (const float*)d_in[6];
    const float* Wh  = (const float*)d_in[7];
    const float* bh  = (const float*)d_in[8];
    const float* Wa  = (const float*)d_in[9];
    const float* ba  = (const float*)d_in[10];
    const float* cv  = (const float*)d_in[11];
    const float* Wfc = (const float*)d_in[12];
    const float* bfc = (const float*)d_in[13];
    float* out = (float*)d_out;

    int eb = (EE + 255) / 256;
    int nb = (NN + 255) / 256;
    int wb = (NN * 32 + 255) / 256;       // warp per node
    int gb = (NN + 63) / 64;              // GEMM tiles
    int ab = (NN + 7) / 8;                // attention

    init_kernel<<<(NN * HH + 255) / 256, 256>>>();
    convx_kernel<<<(NN * CHX / 4 + 255) / 256, 256>>>(x);
    deg_kernel<<<eb, 256>>>(ei, ew);
    dis_kernel<<<nb, 256>>>();
    part_kernel<<<SCAN_B, 1024>>>();
    scanpart_kernel<<<1, 32>>>();
    offs_kernel<<<SCAN_B, 1024>>>();
    fill_kernel<<<eb, 256>>>(ei, ew);
    prop_x_kernel<<<wb, 256>>>();

    for (int t = 0; t < TT; t++) {
        prop64_kernel<<<wb, 256>>>(0);                 // Ah = prop(h16)
        zr_kernel<<<gb, 256>>>(Wz, bz, Wr, br, t);     // z, rh16
        prop64_kernel<<<wb, 256>>>(1);                 // Arh = prop(rh16)
        upd_kernel<<<gb, 256>>>(Wh, bh, t);            // h update + hs store
    }

    attn_kernel<<<ab, 256>>>(Wa, ba, cv, Wfc, bfc, out);
}

// round 4
// speedup vs baseline: 1.5123x; 1.4721x over previous
#include <cuda_runtime.h>
#include <cuda_fp16.h>
#include <cstdint>
#include <math.h>

#define NN 50000
#define FF 16
#define TT 12
#define HH 64
#define EE 1600000
#define CHX 192   // F*T channels of x per node
#define KK 80     // F + H
#define SCAN_B 49 // ceil(NN/1024)

// ---------------- scratch (static device arrays; no allocation) ----------------
__device__ float g_deg[NN];
__device__ float g_dis[NN];
__device__ float g_self[NN];
__device__ int   g_cnt[NN];
__device__ int   g_row[NN];
__device__ int   g_cur[NN];
__device__ int   g_part[64];
__device__ int2  g_edge[EE];              // packed (src, weight-bits)
__device__ __half g_x16[NN * CHX];
__device__ __half g_Xp16[NN * CHX];       // prop(x), fp16, layout [n][t*16+f]
__device__ float g_h[NN * HH];
__device__ __half g_h16[NN * HH];
__device__ float g_z[NN * HH];
__device__ __half g_rh16[NN * HH];
__device__ __half g_Ah16[NN * HH];
__device__ __half g_Arh16[NN * HH];
__device__ __half g_Wzr16[128 * 80];      // n-major: [c][k], c<64 -> Wz, else Wr
__device__ __half g_Wh16[64 * 80];        // n-major: [c][k]
__device__ float g_hs[NN * TT * HH];      // [n][t][c]

// ---------------- helpers ----------------
__device__ __forceinline__ float fast_tanh(float x) {
    float y;
    asm("tanh.approx.f32 %0, %1;" : "=f"(y) : "f"(x));
    return y;
}
__device__ __forceinline__ float fast_sigmoid(float x) {
    return 0.5f * fast_tanh(0.5f * x) + 0.5f;
}
__device__ __forceinline__ uint32_t smem_u32(const void* p) {
    return (uint32_t)__cvta_generic_to_shared(p);
}
__device__ __forceinline__ void ldsm_x4(unsigned* r, uint32_t addr) {
    asm volatile("ldmatrix.sync.aligned.m8n8.x4.shared.b16 {%0,%1,%2,%3}, [%4];\n"
                 : "=r"(r[0]), "=r"(r[1]), "=r"(r[2]), "=r"(r[3]) : "r"(addr));
}
__device__ __forceinline__ void ldsm_x2(unsigned* r, uint32_t addr) {
    asm volatile("ldmatrix.sync.aligned.m8n8.x2.shared.b16 {%0,%1}, [%2];\n"
                 : "=r"(r[0]), "=r"(r[1]) : "r"(addr));
}
__device__ __forceinline__ void mma16816(float* d, const unsigned* a, const unsigned* b) {
    asm volatile("mma.sync.aligned.m16n8k16.row.col.f32.f16.f16.f32 "
                 "{%0,%1,%2,%3}, {%4,%5,%6,%7}, {%8,%9}, {%0,%1,%2,%3};\n"
                 : "+f"(d[0]), "+f"(d[1]), "+f"(d[2]), "+f"(d[3])
                 : "r"(a[0]), "r"(a[1]), "r"(a[2]), "r"(a[3]), "r"(b[0]), "r"(b[1]));
}

// ---------------- prologue kernels ----------------
__global__ void init_kernel() {
    int i = blockIdx.x * blockDim.x + threadIdx.x;
    if (i < NN * HH) { g_h[i] = 0.0f; g_h16[i] = __float2half(0.0f); }
    if (i < NN) { g_deg[i] = 0.0f; g_cnt[i] = 0; }
}

__global__ void convx_kernel(const float* __restrict__ x) {
    int i = blockIdx.x * blockDim.x + threadIdx.x;
    int i4 = i * 4;
    if (i4 + 3 < NN * CHX) {
        float4 v = __ldg((const float4*)&x[i4]);
        __half2* o = (__half2*)&g_x16[i4];
        o[0] = __floats2half2_rn(v.x, v.y);
        o[1] = __floats2half2_rn(v.z, v.w);
    }
}

__global__ void wcvt_kernel(const float* __restrict__ Wz, const float* __restrict__ Wr,
                            const float* __restrict__ Wh) {
    int idx = blockIdx.x * blockDim.x + threadIdx.x;
    if (idx < 128 * 80) {
        int c = idx / 80, k = idx - c * 80;
        float v = (c < 64) ? Wz[k * 64 + c] : Wr[k * 64 + (c - 64)];
        g_Wzr16[c * 80 + k] = __float2half_rn(v);
    }
    if (idx < 64 * 80) {
        int c = idx / 80, k = idx - c * 80;
        g_Wh16[c * 80 + k] = __float2half_rn(Wh[k * 64 + c]);
    }
}

__global__ void deg_kernel(const int* __restrict__ ei, const float* __restrict__ ew) {
    int e = blockIdx.x * blockDim.x + threadIdx.x;
    if (e >= EE) return;
    int d = ei[EE + e];
    atomicAdd(&g_deg[d], ew[e]);
    atomicAdd(&g_cnt[d], 1);
}

__global__ void dis_kernel() {
    int i = blockIdx.x * blockDim.x + threadIdx.x;
    if (i >= NN) return;
    float r = rsqrtf(g_deg[i] + 1.0f);
    g_dis[i] = r;
    g_self[i] = r * r;
}

// hierarchical scan
__global__ void part_kernel() {
    __shared__ int ws[32];
    int tid = threadIdx.x, lane = tid & 31, wid = tid >> 5;
    int i = blockIdx.x * 1024 + tid;
    int v = (i < NN) ? g_cnt[i] : 0;
    #pragma unroll
    for (int o = 16; o; o >>= 1) v += __shfl_xor_sync(0xffffffffu, v, o);
    if (lane == 0) ws[wid] = v;
    __syncthreads();
    if (tid < 32) {
        int s = ws[tid];
        #pragma unroll
        for (int o = 16; o; o >>= 1) s += __shfl_xor_sync(0xffffffffu, s, o);
        if (tid == 0) g_part[blockIdx.x] = s;
    }
}

__global__ void scanpart_kernel() {
    if (threadIdx.x == 0) {
        int run = 0;
        for (int b = 0; b < SCAN_B; b++) { int v = g_part[b]; g_part[b] = run; run += v; }
    }
}

__global__ void offs_kernel() {
    __shared__ int wsum[32];
    int tid = threadIdx.x, lane = tid & 31, wid = tid >> 5;
    int i = blockIdx.x * 1024 + tid;
    int v = (i < NN) ? g_cnt[i] : 0;
    int x = v;
    #pragma unroll
    for (int o = 1; o < 32; o <<= 1) {
        int y = __shfl_up_sync(0xffffffffu, x, o);
        if (lane >= o) x += y;
    }
    if (lane == 31) wsum[wid] = x;
    __syncthreads();
    if (tid < 32) {
        int s = wsum[tid];
        #pragma unroll
        for (int o = 1; o < 32; o <<= 1) {
            int y = __shfl_up_sync(0xffffffffu, s, o);
            if (tid >= o) s += y;
        }
        wsum[tid] = s;
    }
    __syncthreads();
    int excl = g_part[blockIdx.x] + x - v + (wid ? wsum[wid - 1] : 0);
    if (i < NN) { g_row[i] = excl; g_cur[i] = excl; }
}

__global__ void fill_kernel(const int* __restrict__ ei, const float* __restrict__ ew) {
    int e = blockIdx.x * blockDim.x + threadIdx.x;
    if (e >= EE) return;
    int s = ei[e];
    int d = ei[EE + e];
    int p = atomicAdd(&g_cur[d], 1);
    float w = g_dis[s] * ew[e] * g_dis[d];
    g_edge[p] = make_int2(s, __float_as_int(w));
}

// propagate all 192 channels of x once (fp16 gather). warp per node.
__global__ __launch_bounds__(256) void prop_x_kernel() {
    int gw = (blockIdx.x * blockDim.x + threadIdx.x) >> 5;
    if (gw >= NN) return;
    int lane = threadIdx.x & 31;
    int st = g_row[gw], cnt = g_cnt[gw];
    float acc[6] = {0, 0, 0, 0, 0, 0};
    const int2* ep = &g_edge[st];
    int e = 0;
    for (; e + 2 <= cnt; e += 2) {
        int2 e0 = __ldg(&ep[e]), e1 = __ldg(&ep[e + 1]);
        float w0 = __int_as_float(e0.y), w1 = __int_as_float(e1.y);
        const __half2* r0 = (const __half2*)&g_x16[e0.x * CHX];
        const __half2* r1 = (const __half2*)&g_x16[e1.x * CHX];
        #pragma unroll
        for (int j = 0; j < 3; j++) {
            float2 f0 = __half22float2(r0[lane + 32 * j]);
            float2 f1 = __half22float2(r1[lane + 32 * j]);
            acc[2 * j]     += w0 * f0.x + w1 * f1.x;
            acc[2 * j + 1] += w0 * f0.y + w1 * f1.y;
        }
    }
    for (; e < cnt; e++) {
        int2 e0 = __ldg(&ep[e]);
        float w = __int_as_float(e0.y);
        const __half2* r0 = (const __half2*)&g_x16[e0.x * CHX];
        #pragma unroll
        for (int j = 0; j < 3; j++) {
            float2 f0 = __half22float2(r0[lane + 32 * j]);
            acc[2 * j]     += w * f0.x;
            acc[2 * j + 1] += w * f0.y;
        }
    }
    float sn = g_self[gw];
    const __half2* xn = (const __half2*)&g_x16[gw * CHX];
    #pragma unroll
    for (int j = 0; j < 3; j++) {
        float2 f0 = __half22float2(xn[lane + 32 * j]);
        #pragma unroll
        for (int k = 0; k < 2; k++) {
            int c = 2 * (lane + 32 * j) + k;      // c = f*12 + t (x layout [n][f][t])
            float v = acc[2 * j + k] + sn * (k ? f0.y : f0.x);
            int f = c / 12;
            int t = c - f * 12;
            g_Xp16[gw * CHX + t * FF + f] = __float2half_rn(v);  // [n][t][f]
        }
    }
}

// propagate 64 channels (fp16 in/out): which==0: h16 -> Ah16 ; which==1: rh16 -> Arh16.
__global__ __launch_bounds__(256) void prop64_kernel(int which) {
    int gw = (blockIdx.x * blockDim.x + threadIdx.x) >> 5;
    if (gw >= NN) return;
    int lane = threadIdx.x & 31;
    const __half2* in = (const __half2*)(which ? g_rh16 : g_h16);
    __half2* out = (__half2*)(which ? g_Arh16 : g_Ah16);
    int st = g_row[gw], cnt = g_cnt[gw];
    const int2* ep = &g_edge[st];
    float ax = 0.0f, ay = 0.0f;
    int e = 0;
    for (; e + 4 <= cnt; e += 4) {
        int2 e0 = __ldg(&ep[e]),     e1 = __ldg(&ep[e + 1]);
        int2 e2 = __ldg(&ep[e + 2]), e3 = __ldg(&ep[e + 3]);
        float2 v0 = __half22float2(in[e0.x * 32 + lane]);
        float2 v1 = __half22float2(in[e1.x * 32 + lane]);
        float2 v2 = __half22float2(in[e2.x * 32 + lane]);
        float2 v3 = __half22float2(in[e3.x * 32 + lane]);
        float w0 = __int_as_float(e0.y), w1 = __int_as_float(e1.y);
        float w2 = __int_as_float(e2.y), w3 = __int_as_float(e3.y);
        ax += w0 * v0.x + w1 * v1.x + w2 * v2.x + w3 * v3.x;
        ay += w0 * v0.y + w1 * v1.y + w2 * v2.y + w3 * v3.y;
    }
    for (; e < cnt; e++) {
        int2 e0 = __ldg(&ep[e]);
        float w = __int_as_float(e0.y);
        float2 v = __half22float2(in[e0.x * 32 + lane]);
        ax += w * v.x;
        ay += w * v.y;
    }
    float sn = g_self[gw];
    float2 v = __half22float2(in[gw * 32 + lane]);
    ax += sn * v.x;
    ay += sn * v.y;
    out[gw * 32 + lane] = __floats2half2_rn(ax, ay);
}

// ---------------- tensor-core gate kernels ----------------
// zr: C[64 nodes, 128] = [Xp16_t | Ah16] @ [Wz|Wr]  (HMMA, fp32 acc)
__global__ __launch_bounds__(256) void zr_kernel(const float* __restrict__ bz,
                                                 const float* __restrict__ br, int t) {
    __shared__ __align__(16) __half As[64 * 88];
    __shared__ __align__(16) __half Bs[128 * 88];
    int tid = threadIdx.x;
    int n0 = blockIdx.x * 64;

    for (int idx = tid; idx < 640; idx += 256) {
        int m = idx / 10, q = idx - m * 10;
        int n = n0 + m;
        uint4 v = make_uint4(0, 0, 0, 0);
        if (n < NN) {
            if (q < 2) v = *(const uint4*)&g_Xp16[n * CHX + t * 16 + q * 8];
            else       v = *(const uint4*)&g_Ah16[n * HH + (q - 2) * 8];
        }
        *(uint4*)&As[m * 88 + q * 8] = v;
    }
    for (int idx = tid; idx < 1280; idx += 256) {
        int c = idx / 10, q = idx - c * 10;
        *(uint4*)&Bs[c * 88 + q * 8] = *(const uint4*)&g_Wzr16[c * 80 + q * 8];
    }
    __syncthreads();

    int w = tid >> 5, lane = tid & 31;
    int mi = w & 3, nh = w >> 2;          // nh: 0 -> channels 0..63 (z), 1 -> 64..127 (r)
    int m0 = mi * 16;
    float acc[8][4];
    #pragma unroll
    for (int i = 0; i < 8; i++)
        #pragma unroll
        for (int j = 0; j < 4; j++) acc[i][j] = 0.0f;

    uint32_t a_base = smem_u32(As) + (m0 + (lane & 15)) * 176 + (lane >> 4) * 16;
    uint32_t b_base = smem_u32(Bs) + (nh * 64 + (lane & 7)) * 176 + ((lane >> 3) & 1) * 16;

    #pragma unroll
    for (int ks = 0; ks < 5; ks++) {
        unsigned a[4];
        ldsm_x4(a, a_base + ks * 32);
        #pragma unroll
        for (int nj = 0; nj < 8; nj++) {
            unsigned b[2];
            ldsm_x2(b, b_base + nj * 8 * 176 + ks * 32);
            mma16816(acc[nj], a, b);
        }
    }

    int g = lane >> 2, tig = lane & 3;
    #pragma unroll
    for (int nj = 0; nj < 8; nj++) {
        int c = nh * 64 + nj * 8 + tig * 2;
        bool isz = (c < 64);
        float b0v = isz ? __ldg(&bz[c])     : __ldg(&br[c - 64]);
        float b1v = isz ? __ldg(&bz[c + 1]) : __ldg(&br[c - 63]);
        #pragma unroll
        for (int rr = 0; rr < 2; rr++) {
            int n = n0 + m0 + g + rr * 8;
            if (n < NN) {
                float v0 = fast_sigmoid(acc[nj][rr * 2 + 0] + b0v);
                float v1 = fast_sigmoid(acc[nj][rr * 2 + 1] + b1v);
                if (isz) {
                    g_z[n * HH + c]     = v0;
                    g_z[n * HH + c + 1] = v1;
                } else {
                    int cc = c - 64;
                    float2 hf = __half22float2(((const __half2*)g_h16)[(n * HH + cc) >> 1]);
                    ((__half2*)g_rh16)[(n * HH + cc) >> 1] =
                        __floats2half2_rn(v0 * hf.x, v1 * hf.y);
                }
            }
        }
    }
}

// upd: hc = tanh([Xp16_t | Arh16] @ Wh + bh); h = z*h + (1-z)*hc
__global__ __launch_bounds__(256) void upd_kernel(const float* __restrict__ bh, int t) {
    __shared__ __align__(16) __half As[64 * 88];
    __shared__ __align__(16) __half Bs[64 * 88];
    int tid = threadIdx.x;
    int n0 = blockIdx.x * 64;

    for (int idx = tid; idx < 640; idx += 256) {
        int m = idx / 10, q = idx - m * 10;
        int n = n0 + m;
        uint4 v = make_uint4(0, 0, 0, 0);
        if (n < NN) {
            if (q < 2) v = *(const uint4*)&g_Xp16[n * CHX + t * 16 + q * 8];
            else       v = *(const uint4*)&g_Arh16[n * HH + (q - 2) * 8];
        }
        *(uint4*)&As[m * 88 + q * 8] = v;
    }
    for (int idx = tid; idx < 640; idx += 256) {
        int c = idx / 10, q = idx - c * 10;
        *(uint4*)&Bs[c * 88 + q * 8] = *(const uint4*)&g_Wh16[c * 80 + q * 8];
    }
    __syncthreads();

    int w = tid >> 5, lane = tid & 31;
    int mi = w & 3, nh = w >> 2;          // nh: channels nh*32 + nj*8
    int m0 = mi * 16;
    float acc[4][4];
    #pragma unroll
    for (int i = 0; i < 4; i++)
        #pragma unroll
        for (int j = 0; j < 4; j++) acc[i][j] = 0.0f;

    uint32_t a_base = smem_u32(As) + (m0 + (lane & 15)) * 176 + (lane >> 4) * 16;
    uint32_t b_base = smem_u32(Bs) + (nh * 32 + (lane & 7)) * 176 + ((lane >> 3) & 1) * 16;

    #pragma unroll
    for (int ks = 0; ks < 5; ks++) {
        unsigned a[4];
        ldsm_x4(a, a_base + ks * 32);
        #pragma unroll
        for (int nj = 0; nj < 4; nj++) {
            unsigned b[2];
            ldsm_x2(b, b_base + nj * 8 * 176 + ks * 32);
            mma16816(acc[nj], a, b);
        }
    }

    int g = lane >> 2, tig = lane & 3;
    #pragma unroll
    for (int nj = 0; nj < 4; nj++) {
        int c = nh * 32 + nj * 8 + tig * 2;
        float b0v = __ldg(&bh[c]), b1v = __ldg(&bh[c + 1]);
        #pragma unroll
        for (int rr = 0; rr < 2; rr++) {
            int n = n0 + m0 + g + rr * 8;
            if (n < NN) {
                float hc0 = fast_tanh(acc[nj][rr * 2 + 0] + b0v);
                float hc1 = fast_tanh(acc[nj][rr * 2 + 1] + b1v);
                float z0 = g_z[n * HH + c], z1 = g_z[n * HH + c + 1];
                float2 h = *(const float2*)&g_h[n * HH + c];
                float hn0 = z0 * h.x + (1.0f - z0) * hc0;
                float hn1 = z1 * h.y + (1.0f - z1) * hc1;
                *(float2*)&g_h[n * HH + c] = make_float2(hn0, hn1);
                ((__half2*)g_h16)[(n * HH + c) >> 1] = __floats2half2_rn(hn0, hn1);
                *(float2*)&g_hs[n * (TT * HH) + t * HH + c] = make_float2(hn0, hn1);
            }
        }
    }
}

// ---------------- attention + FC ----------------
__global__ __launch_bounds__(256) void attn_kernel(const float* __restrict__ Wa, const float* __restrict__ ba,
                                                   const float* __restrict__ cv, const float* __restrict__ Wfc,
                                                   const float* __restrict__ bfc, float* __restrict__ out) {
    __shared__ float Wa_s[4096];
    __shared__ float ba_s[64], cv_s[64], fc_s[64];
    __shared__ float al_s[8][TT];
    int tid = threadIdx.x;
    for (int i = tid; i < 4096; i += 256) Wa_s[i] = Wa[i];
    if (tid < 64) { ba_s[tid] = ba[tid]; cv_s[tid] = cv[tid]; fc_s[tid] = Wfc[tid]; }
    __syncthreads();

    int warp = tid >> 5, lane = tid & 31;
    int n = blockIdx.x * 8 + warp;
    if (n >= NN) return;
    const float* hb = &g_hs[n * (TT * HH)];

    for (int t = 0; t < TT; t++) {
        float hv0 = __ldg(&hb[t * HH + lane]);
        float hv1 = __ldg(&hb[t * HH + lane + 32]);
        float a0 = ba_s[lane], a1 = ba_s[lane + 32];
        #pragma unroll
        for (int j = 0; j < 32; j++) {
            float hj = __shfl_sync(0xffffffffu, hv0, j);
            a0 += hj * Wa_s[j * HH + lane];
            a1 += hj * Wa_s[j * HH + lane + 32];
        }
        #pragma unroll
        for (int j = 0; j < 32; j++) {
            float hj = __shfl_sync(0xffffffffu, hv1, j);
            a0 += hj * Wa_s[(j + 32) * HH + lane];
            a1 += hj * Wa_s[(j + 32) * HH + lane + 32];
        }
        float al = fast_tanh(a0) * cv_s[lane] + fast_tanh(a1) * cv_s[lane + 32];
        #pragma unroll
        for (int o = 16; o; o >>= 1) al += __shfl_xor_sync(0xffffffffu, al, o);
        if (lane == 0) al_s[warp][t] = al;
    }
    __syncwarp();

    float mx = -1e30f;
    for (int t = 0; t < TT; t++) mx = fmaxf(mx, al_s[warp][t]);
    float ssum = 0.0f;
    for (int t = 0; t < TT; t++) ssum += __expf(al_s[warp][t] - mx);
    float inv = 1.0f / ssum;

    float c0 = 0.0f, c1 = 0.0f;
    for (int t = 0; t < TT; t++) {
        float w = __expf(al_s[warp][t] - mx) * inv;
        c0 += w * __ldg(&hb[t * HH + lane]);
        c1 += w * __ldg(&hb[t * HH + lane + 32]);
    }
    float o = c0 * fc_s[lane] + c1 * fc_s[lane + 32];
    #pragma unroll
    for (int off = 16; off; off >>= 1) o += __shfl_xor_sync(0xffffffffu, o, off);
    if (lane == 0) out[n] = o + bfc[0];
}

// ---------------- launcher ----------------
extern "C" void kernel_launch(void* const* d_in, const int* in_sizes, int n_in,
                              void* d_out, int out_size) {
    const float* x   = (const float*)d_in[0];
    const int*   ei  = (const int*)d_in[1];
    const float* ew  = (const float*)d_in[2];
    const float* Wz  = (const float*)d_in[3];
    const float* bz  = (const float*)d_in[4];
    const float* Wr  = (const float*)d_in[5];
    const float* br  = (const float*)d_in[6];
    const float* Wh  = (const float*)d_in[7];
    const float* bh  = (const float*)d_in[8];
    const float* Wa  = (const float*)d_in[9];
    const float* ba  = (const float*)d_in[10];
    const float* cv  = (const float*)d_in[11];
    const float* Wfc = (const float*)d_in[12];
    const float* bfc = (const float*)d_in[13];
    float* out = (float*)d_out;

    int eb = (EE + 255) / 256;
    int nb = (NN + 255) / 256;
    int wb = (NN * 32 + 255) / 256;       // warp per node
    int gb = (NN + 63) / 64;              // GEMM tiles
    int ab = (NN + 7) / 8;                // attention

    init_kernel<<<(NN * HH + 255) / 256, 256>>>();
    convx_kernel<<<(NN * CHX / 4 + 255) / 256, 256>>>(x);
    wcvt_kernel<<<(128 * 80 + 255) / 256, 256>>>(Wz, Wr, Wh);
    deg_kernel<<<eb, 256>>>(ei, ew);
    dis_kernel<<<nb, 256>>>();
    part_kernel<<<SCAN_B, 1024>>>();
    scanpart_kernel<<<1, 32>>>();
    offs_kernel<<<SCAN_B, 1024>>>();
    fill_kernel<<<eb, 256>>>(ei, ew);
    prop_x_kernel<<<wb, 256>>>();

    for (int t = 0; t < TT; t++) {
        prop64_kernel<<<wb, 256>>>(0);             // Ah16 = prop(h16)
        zr_kernel<<<gb, 256>>>(bz, br, t);         // z, rh16 (HMMA)
        prop64_kernel<<<wb, 256>>>(1);             // Arh16 = prop(rh16)
        upd_kernel<<<gb, 256>>>(bh, t);            // h update (HMMA)
    }

    attn_kernel<<<ab, 256>>>(Wa, ba, cv, Wfc, bfc, out);
}

// round 5
// speedup vs baseline: 1.5605x; 1.0319x over previous
#include <cuda_runtime.h>
#include <cuda_fp16.h>
#include <cstdint>
#include <math.h>

#define NN 50000
#define FF 16
#define TT 12
#define HH 64
#define EE 1600000
#define CHX 192   // F*T channels of x per node
#define SCAN_B 49 // ceil(NN/1024)

// ---------------- scratch (static device arrays; no allocation) ----------------
__device__ float g_deg[NN];
__device__ float g_dis[NN];
__device__ float g_self[NN];
__device__ int   g_cnt[NN];
__device__ int   g_row[NN];
__device__ int   g_cur[NN];
__device__ int   g_part[64];
__device__ int2  g_edge[EE];              // packed (src, weight-bits)
__device__ __half g_x16[NN * CHX];
__device__ __half g_Xp16[NN * CHX];       // prop(x), fp16, layout [n][t*16+f]
__device__ float g_h[NN * HH];
__device__ __half g_h16[NN * HH];
__device__ float g_z[NN * HH];
__device__ __half g_rh16[NN * HH];
__device__ __half g_Wzr16[128 * 80];      // n-major: [c][k], c<64 -> Wz, else Wr
__device__ __half g_Wh16[64 * 80];        // n-major: [c][k]
__device__ __half g_hs16[NN * TT * HH];   // [n][t][c] fp16

// ---------------- helpers ----------------
__device__ __forceinline__ float fast_tanh(float x) {
    float y;
    asm("tanh.approx.f32 %0, %1;" : "=f"(y) : "f"(x));
    return y;
}
__device__ __forceinline__ float fast_sigmoid(float x) {
    return 0.5f * fast_tanh(0.5f * x) + 0.5f;
}
__device__ __forceinline__ uint32_t smem_u32(const void* p) {
    return (uint32_t)__cvta_generic_to_shared(p);
}
__device__ __forceinline__ void ldsm_x4(unsigned* r, uint32_t addr) {
    asm volatile("ldmatrix.sync.aligned.m8n8.x4.shared.b16 {%0,%1,%2,%3}, [%4];\n"
                 : "=r"(r[0]), "=r"(r[1]), "=r"(r[2]), "=r"(r[3]) : "r"(addr));
}
__device__ __forceinline__ void ldsm_x2(unsigned* r, uint32_t addr) {
    asm volatile("ldmatrix.sync.aligned.m8n8.x2.shared.b16 {%0,%1}, [%2];\n"
                 : "=r"(r[0]), "=r"(r[1]) : "r"(addr));
}
__device__ __forceinline__ void mma16816(float* d, const unsigned* a, const unsigned* b) {
    asm volatile("mma.sync.aligned.m16n8k16.row.col.f32.f16.f16.f32 "
                 "{%0,%1,%2,%3}, {%4,%5,%6,%7}, {%8,%9}, {%0,%1,%2,%3};\n"
                 : "+f"(d[0]), "+f"(d[1]), "+f"(d[2]), "+f"(d[3])
                 : "r"(a[0]), "r"(a[1]), "r"(a[2]), "r"(a[3]), "r"(b[0]), "r"(b[1]));
}

// gather-propagate one node's 64 channels (this lane holds channels 2*lane, 2*lane+1)
__device__ __forceinline__ float2 prop_node(int n, int lane, const __half2* __restrict__ in) {
    int st = g_row[n], cnt = g_cnt[n];
    const int2* ep = &g_edge[st];
    float ax = 0.0f, ay = 0.0f;
    int e = 0;
    for (; e + 4 <= cnt; e += 4) {
        int2 e0 = __ldg(&ep[e]),     e1 = __ldg(&ep[e + 1]);
        int2 e2 = __ldg(&ep[e + 2]), e3 = __ldg(&ep[e + 3]);
        float2 v0 = __half22float2(in[e0.x * 32 + lane]);
        float2 v1 = __half22float2(in[e1.x * 32 + lane]);
        float2 v2 = __half22float2(in[e2.x * 32 + lane]);
        float2 v3 = __half22float2(in[e3.x * 32 + lane]);
        float w0 = __int_as_float(e0.y), w1 = __int_as_float(e1.y);
        float w2 = __int_as_float(e2.y), w3 = __int_as_float(e3.y);
        ax += w0 * v0.x + w1 * v1.x + w2 * v2.x + w3 * v3.x;
        ay += w0 * v0.y + w1 * v1.y + w2 * v2.y + w3 * v3.y;
    }
    for (; e < cnt; e++) {
        int2 e0 = __ldg(&ep[e]);
        float w = __int_as_float(e0.y);
        float2 v = __half22float2(in[e0.x * 32 + lane]);
        ax += w * v.x;
        ay += w * v.y;
    }
    float sn = g_self[n];
    float2 v = __half22float2(in[n * 32 + lane]);
    ax += sn * v.x;
    ay += sn * v.y;
    return make_float2(ax, ay);
}

// ---------------- prologue kernels ----------------
__global__ void init_kernel() {
    int i = blockIdx.x * blockDim.x + threadIdx.x;
    if (i < NN * HH) { g_h[i] = 0.0f; g_h16[i] = __float2half(0.0f); }
    if (i < NN) { g_deg[i] = 0.0f; g_cnt[i] = 0; }
}

__global__ void convx_kernel(const float* __restrict__ x) {
    int i = blockIdx.x * blockDim.x + threadIdx.x;
    int i4 = i * 4;
    if (i4 + 3 < NN * CHX) {
        float4 v = __ldg((const float4*)&x[i4]);
        __half2* o = (__half2*)&g_x16[i4];
        o[0] = __floats2half2_rn(v.x, v.y);
        o[1] = __floats2half2_rn(v.z, v.w);
    }
}

__global__ void wcvt_kernel(const float* __restrict__ Wz, const float* __restrict__ Wr,
                            const float* __restrict__ Wh) {
    int idx = blockIdx.x * blockDim.x + threadIdx.x;
    if (idx < 128 * 80) {
        int c = idx / 80, k = idx - c * 80;
        float v = (c < 64) ? Wz[k * 64 + c] : Wr[k * 64 + (c - 64)];
        g_Wzr16[c * 80 + k] = __float2half_rn(v);
    }
    if (idx < 64 * 80) {
        int c = idx / 80, k = idx - c * 80;
        g_Wh16[c * 80 + k] = __float2half_rn(Wh[k * 64 + c]);
    }
}

__global__ void deg_kernel(const int* __restrict__ ei, const float* __restrict__ ew) {
    int e = blockIdx.x * blockDim.x + threadIdx.x;
    if (e >= EE) return;
    int d = ei[EE + e];
    atomicAdd(&g_deg[d], ew[e]);
    atomicAdd(&g_cnt[d], 1);
}

__global__ void dis_kernel() {
    int i = blockIdx.x * blockDim.x + threadIdx.x;
    if (i >= NN) return;
    float r = rsqrtf(g_deg[i] + 1.0f);
    g_dis[i] = r;
    g_self[i] = r * r;
}

// hierarchical scan
__global__ void part_kernel() {
    __shared__ int ws[32];
    int tid = threadIdx.x, lane = tid & 31, wid = tid >> 5;
    int i = blockIdx.x * 1024 + tid;
    int v = (i < NN) ? g_cnt[i] : 0;
    #pragma unroll
    for (int o = 16; o; o >>= 1) v += __shfl_xor_sync(0xffffffffu, v, o);
    if (lane == 0) ws[wid] = v;
    __syncthreads();
    if (tid < 32) {
        int s = ws[tid];
        #pragma unroll
        for (int o = 16; o; o >>= 1) s += __shfl_xor_sync(0xffffffffu, s, o);
        if (tid == 0) g_part[blockIdx.x] = s;
    }
}

__global__ void scanpart_kernel() {
    if (threadIdx.x == 0) {
        int run = 0;
        for (int b = 0; b < SCAN_B; b++) { int v = g_part[b]; g_part[b] = run; run += v; }
    }
}

__global__ void offs_kernel() {
    __shared__ int wsum[32];
    int tid = threadIdx.x, lane = tid & 31, wid = tid >> 5;
    int i = blockIdx.x * 1024 + tid;
    int v = (i < NN) ? g_cnt[i] : 0;
    int x = v;
    #pragma unroll
    for (int o = 1; o < 32; o <<= 1) {
        int y = __shfl_up_sync(0xffffffffu, x, o);
        if (lane >= o) x += y;
    }
    if (lane == 31) wsum[wid] = x;
    __syncthreads();
    if (tid < 32) {
        int s = wsum[tid];
        #pragma unroll
        for (int o = 1; o < 32; o <<= 1) {
            int y = __shfl_up_sync(0xffffffffu, s, o);
            if (tid >= o) s += y;
        }
        wsum[tid] = s;
    }
    __syncthreads();
    int excl = g_part[blockIdx.x] + x - v + (wid ? wsum[wid - 1] : 0);
    if (i < NN) { g_row[i] = excl; g_cur[i] = excl; }
}

__global__ void fill_kernel(const int* __restrict__ ei, const float* __restrict__ ew) {
    int e = blockIdx.x * blockDim.x + threadIdx.x;
    if (e >= EE) return;
    int s = ei[e];
    int d = ei[EE + e];
    int p = atomicAdd(&g_cur[d], 1);
    float w = g_dis[s] * ew[e] * g_dis[d];
    g_edge[p] = make_int2(s, __float_as_int(w));
}

// propagate all 192 channels of x once (fp16 gather). warp per node.
__global__ __launch_bounds__(256) void prop_x_kernel() {
    int gw = (blockIdx.x * blockDim.x + threadIdx.x) >> 5;
    if (gw >= NN) return;
    int lane = threadIdx.x & 31;
    int st = g_row[gw], cnt = g_cnt[gw];
    float acc[6] = {0, 0, 0, 0, 0, 0};
    const int2* ep = &g_edge[st];
    int e = 0;
    for (; e + 2 <= cnt; e += 2) {
        int2 e0 = __ldg(&ep[e]), e1 = __ldg(&ep[e + 1]);
        float w0 = __int_as_float(e0.y), w1 = __int_as_float(e1.y);
        const __half2* r0 = (const __half2*)&g_x16[e0.x * CHX];
        const __half2* r1 = (const __half2*)&g_x16[e1.x * CHX];
        #pragma unroll
        for (int j = 0; j < 3; j++) {
            float2 f0 = __half22float2(r0[lane + 32 * j]);
            float2 f1 = __half22float2(r1[lane + 32 * j]);
            acc[2 * j]     += w0 * f0.x + w1 * f1.x;
            acc[2 * j + 1] += w0 * f0.y + w1 * f1.y;
        }
    }
    for (; e < cnt; e++) {
        int2 e0 = __ldg(&ep[e]);
        float w = __int_as_float(e0.y);
        const __half2* r0 = (const __half2*)&g_x16[e0.x * CHX];
        #pragma unroll
        for (int j = 0; j < 3; j++) {
            float2 f0 = __half22float2(r0[lane + 32 * j]);
            acc[2 * j]     += w * f0.x;
            acc[2 * j + 1] += w * f0.y;
        }
    }
    float sn = g_self[gw];
    const __half2* xn = (const __half2*)&g_x16[gw * CHX];
    #pragma unroll
    for (int j = 0; j < 3; j++) {
        float2 f0 = __half22float2(xn[lane + 32 * j]);
        #pragma unroll
        for (int k = 0; k < 2; k++) {
            int c = 2 * (lane + 32 * j) + k;      // c = f*12 + t (x layout [n][f][t])
            float v = acc[2 * j + k] + sn * (k ? f0.y : f0.x);
            int f = c / 12;
            int t = c - f * 12;
            g_Xp16[gw * CHX + t * FF + f] = __float2half_rn(v);  // [n][t][f]
        }
    }
}

// ---------------- fused prop + gate kernels ----------------
// A: prop(h16) gathered straight into smem rows 16..79, then
//    C[64,128] = [Xp16_t | Ah] @ [Wz|Wr]  (HMMA) -> z, rh16
__global__ __launch_bounds__(256) void prop_zr_kernel(const float* __restrict__ bz,
                                                      const float* __restrict__ br, int t) {
    __shared__ __align__(16) __half As[64 * 88];
    __shared__ __align__(16) __half Bs[128 * 88];
    int tid = threadIdx.x;
    int n0 = blockIdx.x * 64;
    int warp = tid >> 5, lane = tid & 31;

    for (int idx = tid; idx < 1280; idx += 256) {
        int c = idx / 10, q = idx - c * 10;
        *(uint4*)&Bs[c * 88 + q * 8] = *(const uint4*)&g_Wzr16[c * 80 + q * 8];
    }
    for (int idx = tid; idx < 128; idx += 256) {
        int m = idx >> 1, q = idx & 1;
        int n = n0 + m;
        uint4 v = make_uint4(0, 0, 0, 0);
        if (n < NN) v = *(const uint4*)&g_Xp16[n * CHX + t * 16 + q * 8];
        *(uint4*)&As[m * 88 + q * 8] = v;
    }

    // prop phase: each warp handles 8 nodes, result -> As rows 16..79
    #pragma unroll 1
    for (int i = 0; i < 8; i++) {
        int m = warp * 8 + i;
        int n = n0 + m;
        float2 a = make_float2(0.0f, 0.0f);
        if (n < NN) a = prop_node(n, lane, (const __half2*)g_h16);
        ((__half2*)&As[m * 88 + 16])[lane] = __floats2half2_rn(a.x, a.y);
    }
    __syncthreads();

    int mi = warp & 3, nh = warp >> 2;    // nh: 0 -> z channels, 1 -> r channels
    int m0 = mi * 16;
    float acc[8][4];
    #pragma unroll
    for (int i = 0; i < 8; i++)
        #pragma unroll
        for (int j = 0; j < 4; j++) acc[i][j] = 0.0f;

    uint32_t a_base = smem_u32(As) + (m0 + (lane & 15)) * 176 + (lane >> 4) * 16;
    uint32_t b_base = smem_u32(Bs) + (nh * 64 + (lane & 7)) * 176 + ((lane >> 3) & 1) * 16;

    #pragma unroll
    for (int ks = 0; ks < 5; ks++) {
        unsigned a[4];
        ldsm_x4(a, a_base + ks * 32);
        #pragma unroll
        for (int nj = 0; nj < 8; nj++) {
            unsigned b[2];
            ldsm_x2(b, b_base + nj * 8 * 176 + ks * 32);
            mma16816(acc[nj], a, b);
        }
    }

    int g = lane >> 2, tig = lane & 3;
    #pragma unroll
    for (int nj = 0; nj < 8; nj++) {
        int c = nh * 64 + nj * 8 + tig * 2;
        bool isz = (c < 64);
        float b0v = isz ? __ldg(&bz[c])     : __ldg(&br[c - 64]);
        float b1v = isz ? __ldg(&bz[c + 1]) : __ldg(&br[c - 63]);
        #pragma unroll
        for (int rr = 0; rr < 2; rr++) {
            int n = n0 + m0 + g + rr * 8;
            if (n < NN) {
                float v0 = fast_sigmoid(acc[nj][rr * 2 + 0] + b0v);
                float v1 = fast_sigmoid(acc[nj][rr * 2 + 1] + b1v);
                if (isz) {
                    g_z[n * HH + c]     = v0;
                    g_z[n * HH + c + 1] = v1;
                } else {
                    int cc = c - 64;
                    float2 hf = __half22float2(((const __half2*)g_h16)[(n * HH + cc) >> 1]);
                    ((__half2*)g_rh16)[(n * HH + cc) >> 1] =
                        __floats2half2_rn(v0 * hf.x, v1 * hf.y);
                }
            }
        }
    }
}

// B: prop(rh16) -> smem, hc = tanh([Xp16_t | Arh] @ Wh + bh); h = z*h + (1-z)*hc
__global__ __launch_bounds__(256) void prop_upd_kernel(const float* __restrict__ bh, int t) {
    __shared__ __align__(16) __half As[64 * 88];
    __shared__ __align__(16) __half Bs[64 * 88];
    int tid = threadIdx.x;
    int n0 = blockIdx.x * 64;
    int warp = tid >> 5, lane = tid & 31;

    for (int idx = tid; idx < 640; idx += 256) {
        int c = idx / 10, q = idx - c * 10;
        *(uint4*)&Bs[c * 88 + q * 8] = *(const uint4*)&g_Wh16[c * 80 + q * 8];
    }
    for (int idx = tid; idx < 128; idx += 256) {
        int m = idx >> 1, q = idx & 1;
        int n = n0 + m;
        uint4 v = make_uint4(0, 0, 0, 0);
        if (n < NN) v = *(const uint4*)&g_Xp16[n * CHX + t * 16 + q * 8];
        *(uint4*)&As[m * 88 + q * 8] = v;
    }

    #pragma unroll 1
    for (int i = 0; i < 8; i++) {
        int m = warp * 8 + i;
        int n = n0 + m;
        float2 a = make_float2(0.0f, 0.0f);
        if (n < NN) a = prop_node(n, lane, (const __half2*)g_rh16);
        ((__half2*)&As[m * 88 + 16])[lane] = __floats2half2_rn(a.x, a.y);
    }
    __syncthreads();

    int mi = warp & 3, nh = warp >> 2;
    int m0 = mi * 16;
    float acc[4][4];
    #pragma unroll
    for (int i = 0; i < 4; i++)
        #pragma unroll
        for (int j = 0; j < 4; j++) acc[i][j] = 0.0f;

    uint32_t a_base = smem_u32(As) + (m0 + (lane & 15)) * 176 + (lane >> 4) * 16;
    uint32_t b_base = smem_u32(Bs) + (nh * 32 + (lane & 7)) * 176 + ((lane >> 3) & 1) * 16;

    #pragma unroll
    for (int ks = 0; ks < 5; ks++) {
        unsigned a[4];
        ldsm_x4(a, a_base + ks * 32);
        #pragma unroll
        for (int nj = 0; nj < 4; nj++) {
            unsigned b[2];
            ldsm_x2(b, b_base + nj * 8 * 176 + ks * 32);
            mma16816(acc[nj], a, b);
        }
    }

    int g = lane >> 2, tig = lane & 3;
    #pragma unroll
    for (int nj = 0; nj < 4; nj++) {
        int c = nh * 32 + nj * 8 + tig * 2;
        float b0v = __ldg(&bh[c]), b1v = __ldg(&bh[c + 1]);
        #pragma unroll
        for (int rr = 0; rr < 2; rr++) {
            int n = n0 + m0 + g + rr * 8;
            if (n < NN) {
                float hc0 = fast_tanh(acc[nj][rr * 2 + 0] + b0v);
                float hc1 = fast_tanh(acc[nj][rr * 2 + 1] + b1v);
                float z0 = g_z[n * HH + c], z1 = g_z[n * HH + c + 1];
                float2 h = *(const float2*)&g_h[n * HH + c];
                float hn0 = z0 * h.x + (1.0f - z0) * hc0;
                float hn1 = z1 * h.y + (1.0f - z1) * hc1;
                *(float2*)&g_h[n * HH + c] = make_float2(hn0, hn1);
                __half2 hh = __floats2half2_rn(hn0, hn1);
                ((__half2*)g_h16)[(n * HH + c) >> 1] = hh;
                ((__half2*)g_hs16)[(n * (TT * HH) + t * HH + c) >> 1] = hh;
            }
        }
    }
}

// ---------------- attention + FC (fp16 hs) ----------------
__global__ __launch_bounds__(256) void attn_kernel(const float* __restrict__ Wa, const float* __restrict__ ba,
                                                   const float* __restrict__ cv, const float* __restrict__ Wfc,
                                                   const float* __restrict__ bfc, float* __restrict__ out) {
    __shared__ float Wa_s[4096];
    __shared__ float ba_s[64], cv_s[64], fc_s[64];
    __shared__ float al_s[8][TT];
    int tid = threadIdx.x;
    for (int i = tid; i < 4096; i += 256) Wa_s[i] = Wa[i];
    if (tid < 64) { ba_s[tid] = ba[tid]; cv_s[tid] = cv[tid]; fc_s[tid] = Wfc[tid]; }
    __syncthreads();

    int warp = tid >> 5, lane = tid & 31;
    int n = blockIdx.x * 8 + warp;
    if (n >= NN) return;
    const uint32_t* hb = (const uint32_t*)&g_hs16[n * (TT * HH)];  // 32 half2 per t

    for (int t = 0; t < TT; t++) {
        uint32_t hraw = __ldg(&hb[t * 32 + lane]);  // channels 2*lane, 2*lane+1
        float a0 = ba_s[lane], a1 = ba_s[lane + 32];
        #pragma unroll
        for (int j = 0; j < 32; j++) {
            uint32_t hj = __shfl_sync(0xffffffffu, hraw, j);
            float2 f = __half22float2(*(__half2*)&hj);
            a0 += f.x * Wa_s[(2 * j) * HH + lane]      + f.y * Wa_s[(2 * j + 1) * HH + lane];
            a1 += f.x * Wa_s[(2 * j) * HH + lane + 32] + f.y * Wa_s[(2 * j + 1) * HH + lane + 32];
        }
        float al = fast_tanh(a0) * cv_s[lane] + fast_tanh(a1) * cv_s[lane + 32];
        #pragma unroll
        for (int o = 16; o; o >>= 1) al += __shfl_xor_sync(0xffffffffu, al, o);
        if (lane == 0) al_s[warp][t] = al;
    }
    __syncwarp();

    float mx = -1e30f;
    for (int t = 0; t < TT; t++) mx = fmaxf(mx, al_s[warp][t]);
    float ssum = 0.0f;
    for (int t = 0; t < TT; t++) ssum += __expf(al_s[warp][t] - mx);
    float inv = 1.0f / ssum;

    float cx = 0.0f, cy = 0.0f;
    for (int t = 0; t < TT; t++) {
        float w = __expf(al_s[warp][t] - mx) * inv;
        uint32_t hraw = __ldg(&hb[t * 32 + lane]);
        float2 f = __half22float2(*(__half2*)&hraw);
        cx += w * f.x;
        cy += w * f.y;
    }
    float o = cx * fc_s[2 * lane] + cy * fc_s[2 * lane + 1];
    #pragma unroll
    for (int off = 16; off; off >>= 1) o += __shfl_xor_sync(0xffffffffu, o, off);
    if (lane == 0) out[n] = o + bfc[0];
}

// ---------------- launcher ----------------
extern "C" void kernel_launch(void* const* d_in, const int* in_sizes, int n_in,
                              void* d_out, int out_size) {
    const float* x   = (const float*)d_in[0];
    const int*   ei  = (const int*)d_in[1];
    const float* ew  = (const float*)d_in[2];
    const float* Wz  = (const float*)d_in[3];
    const float* bz  = (const float*)d_in[4];
    const float* Wr  = (const float*)d_in[5];
    const float* br  = (const float*)d_in[6];
    const float* Wh  = (const float*)d_in[7];
    const float* bh  = (const float*)d_in[8];
    const float* Wa  = (const float*)d_in[9];
    const float* ba  = (const float*)d_in[10];
    const float* cv  = (const float*)d_in[11];
    const float* Wfc = (const float*)d_in[12];
    const float* bfc = (const float*)d_in[13];
    float* out = (float*)d_out;

    int eb = (EE + 255) / 256;
    int nb = (NN + 255) / 256;
    int wb = (NN * 32 + 255) / 256;       // warp per node
    int gb = (NN + 63) / 64;              // fused tiles
    int ab = (NN + 7) / 8;                // attention

    init_kernel<<<(NN * HH + 255) / 256, 256>>>();
    convx_kernel<<<(NN * CHX / 4 + 255) / 256, 256>>>(x);
    wcvt_kernel<<<(128 * 80 + 255) / 256, 256>>>(Wz, Wr, Wh);
    deg_kernel<<<eb, 256>>>(ei, ew);
    dis_kernel<<<nb, 256>>>();
    part_kernel<<<SCAN_B, 1024>>>();
    scanpart_kernel<<<1, 32>>>();
    offs_kernel<<<SCAN_B, 1024>>>();
    fill_kernel<<<eb, 256>>>(ei, ew);
    prop_x_kernel<<<wb, 256>>>();

    for (int t = 0; t < TT; t++) {
        prop_zr_kernel<<<gb, 256>>>(bz, br, t);    // prop(h) + z/r gates
        prop_upd_kernel<<<gb, 256>>>(bh, t);       // prop(rh) + h update
    }

    attn_kernel<<<ab, 256>>>(Wa, ba, cv, Wfc, bfc, out);
}